// round 1
// baseline (speedup 1.0000x reference)
#include <cuda_runtime.h>
#include <cuda_bf16.h>
#include <cstdint>

#define N1 262144
#define N2 65536
#define N3 16384
#define E1 524288
#define E2 262144
#define HD 256     // HEADS*HID
#define HID 64
#define HEADS 4
#define OUTD 64
#define IND 128
#define NEG_SLOPE 0.2f

// ---------------- device scratch (static, allowed) ----------------
__device__ float g_h1[(size_t)N1 * HD];     // 256 MB  h_src layer1
__device__ float g_as1[(size_t)N1 * HEADS]; // a_src layer1
__device__ float g_ad1[(size_t)N2 * HEADS]; // a_dst layer1
__device__ float g_p1[(size_t)E1 * HEADS];  // per-edge exp()
__device__ float g_den1[(size_t)N2 * HEADS];
__device__ float g_out1[(size_t)N2 * HD];   // 64 MB  layer1 aggregated (pre-BN)
__device__ float g_h2[(size_t)N2 * OUTD];   // 16 MB  h2_src
__device__ float g_as2[N2];
__device__ float g_ad2[N3];
__device__ float g_p2[E2];
__device__ float g_den2[N3];

__device__ float g_v1d[IND * HEADS];   // folded W1_dst @ att1_dst  [k][h]
__device__ float g_v2s[HD];            // folded W2_src @ att2_src
__device__ float g_v2d[HD];            // folded W2_dst @ att2_dst
__device__ float g_bnscale[HD];
__device__ float g_bnshift[HD];

// ---------------- fold kernel (tiny) ----------------
__global__ void fold_kernel(const float* __restrict__ W1d, const float* __restrict__ a1d,
                            const float* __restrict__ W2s, const float* __restrict__ W2d,
                            const float* __restrict__ a2s, const float* __restrict__ a2d,
                            const float* __restrict__ b1, const float* __restrict__ gamma,
                            const float* __restrict__ beta, const float* __restrict__ mean,
                            const float* __restrict__ var) {
    int t = threadIdx.x;  // 512 threads
    // v1d: t = k*4 + h, k<128, h<4
    {
        int k = t >> 2, h = t & 3;
        float d1 = 0.f;
        for (int c = 0; c < HID; c++)
            d1 += W1d[k * HD + h * HID + c] * a1d[h * HID + c];
        g_v1d[t] = d1;
    }
    if (t < HD) {
        float s2 = 0.f, d2 = 0.f;
        for (int c = 0; c < OUTD; c++) {
            s2 += W2s[t * OUTD + c] * a2s[c];
            d2 += W2d[t * OUTD + c] * a2d[c];
        }
        g_v2s[t] = s2;
        g_v2d[t] = d2;
        float sc = gamma[t] * rsqrtf(var[t] + 1e-5f);
        g_bnscale[t] = sc;
        g_bnshift[t] = beta[t] + (b1[t] - mean[t]) * sc;
    }
}

// ---------------- GEMM1: h_src = x @ W1_src, plus a_src fold ----------------
// tile: 128 rows x 256 cols, 512 threads, thread = 4 rows x 16 cols
#define G1_SMEM ((IND * HD + IND * 132 + IND * HEADS) * 4)
__global__ __launch_bounds__(512) void gemm1_kernel(const float* __restrict__ x,
                                                    const float* __restrict__ W,
                                                    const float* __restrict__ att) {
    extern __shared__ float sm[];
    float* Wsm  = sm;                 // 128*256
    float* xs   = sm + IND * HD;      // 128*132 transposed x tile: xs[k*132 + r]
    float* asum = xs + IND * 132;     // 128*4 a_src reduction
    int tid = threadIdx.x;
    int row0 = blockIdx.x * 128;

    for (int i = tid; i < IND * HD; i += 512) Wsm[i] = W[i];
    for (int i = tid; i < IND * IND; i += 512) {
        int r = i >> 7, k = i & 127;
        xs[k * 132 + r] = x[(size_t)(row0 + r) * IND + k];
    }
    asum[tid] = 0.f;
    __syncthreads();

    int tc = tid & 15, tr = tid >> 4;   // tc: col chunk (16 cols), tr: row chunk (4 rows)
    int r0 = tr * 4, c0 = tc * 16;
    float acc[4][16];
#pragma unroll
    for (int a = 0; a < 4; a++)
#pragma unroll
        for (int b = 0; b < 16; b++) acc[a][b] = 0.f;

#pragma unroll 4
    for (int k = 0; k < IND; k++) {
        float4 xv = *(const float4*)(xs + k * 132 + r0);
        const float* wr = Wsm + k * HD + c0;
        float4 w0 = *(const float4*)(wr);
        float4 w1 = *(const float4*)(wr + 4);
        float4 w2 = *(const float4*)(wr + 8);
        float4 w3 = *(const float4*)(wr + 12);
        float wv[16] = {w0.x, w0.y, w0.z, w0.w, w1.x, w1.y, w1.z, w1.w,
                        w2.x, w2.y, w2.z, w2.w, w3.x, w3.y, w3.z, w3.w};
        float xr[4] = {xv.x, xv.y, xv.z, xv.w};
#pragma unroll
        for (int a = 0; a < 4; a++)
#pragma unroll
            for (int b = 0; b < 16; b++) acc[a][b] += xr[a] * wv[b];
    }

    // a_src partial: head = c0/64
    int head = tc >> 2;
    const float* av = att + head * HID + (tc & 3) * 16;
    float attv[16];
#pragma unroll
    for (int j = 0; j < 16; j++) attv[j] = av[j];
#pragma unroll
    for (int a = 0; a < 4; a++) {
        float pa = 0.f;
#pragma unroll
        for (int j = 0; j < 16; j++) pa += acc[a][j] * attv[j];
        atomicAdd(&asum[(r0 + a) * HEADS + head], pa);
    }

    // store h_src
#pragma unroll
    for (int a = 0; a < 4; a++) {
        float* o = g_h1 + (size_t)(row0 + r0 + a) * HD + c0;
        *(float4*)(o)      = make_float4(acc[a][0], acc[a][1], acc[a][2], acc[a][3]);
        *(float4*)(o + 4)  = make_float4(acc[a][4], acc[a][5], acc[a][6], acc[a][7]);
        *(float4*)(o + 8)  = make_float4(acc[a][8], acc[a][9], acc[a][10], acc[a][11]);
        *(float4*)(o + 12) = make_float4(acc[a][12], acc[a][13], acc[a][14], acc[a][15]);
    }
    __syncthreads();
    g_as1[(size_t)row0 * HEADS + tid] = asum[tid];
}

// ---------------- a_dst layer1: warp per row over x[:N2] ----------------
__global__ void adst1_kernel(const float* __restrict__ x) {
    int gw = (blockIdx.x * blockDim.x + threadIdx.x) >> 5;
    int lane = threadIdx.x & 31;
    if (gw >= N2) return;
    float4 xv = *(const float4*)(x + (size_t)gw * IND + lane * 4);
    float a[4] = {0.f, 0.f, 0.f, 0.f};
    float xr[4] = {xv.x, xv.y, xv.z, xv.w};
#pragma unroll
    for (int i = 0; i < 4; i++) {
        int k = lane * 4 + i;
#pragma unroll
        for (int h = 0; h < 4; h++) a[h] += xr[i] * g_v1d[k * HEADS + h];
    }
#pragma unroll
    for (int off = 16; off > 0; off >>= 1)
#pragma unroll
        for (int h = 0; h < 4; h++) a[h] += __shfl_down_sync(0xffffffffu, a[h], off);
    if (lane == 0)
        *(float4*)(g_ad1 + (size_t)gw * HEADS) = make_float4(a[0], a[1], a[2], a[3]);
}

// ---------------- edge passes layer 1 ----------------
__global__ void e1p1_kernel(const int* __restrict__ src, const int* __restrict__ dst) {
    int e = blockIdx.x * blockDim.x + threadIdx.x;
    if (e >= E1) return;
    int s = src[e], d = dst[e];
    float4 as = *(const float4*)(g_as1 + (size_t)s * HEADS);
    float4 ad = *(const float4*)(g_ad1 + (size_t)d * HEADS);
    float ev[4] = {as.x + ad.x, as.y + ad.y, as.z + ad.z, as.w + ad.w};
    float p[4];
#pragma unroll
    for (int h = 0; h < 4; h++) {
        float ee = ev[h];
        ee = ee > 0.f ? ee : NEG_SLOPE * ee;
        p[h] = expf(ee);
    }
    *(float4*)(g_p1 + (size_t)e * HEADS) = make_float4(p[0], p[1], p[2], p[3]);
#pragma unroll
    for (int h = 0; h < 4; h++) atomicAdd(&g_den1[(size_t)d * HEADS + h], p[h]);
}

// warp per edge: gather 256-ch row from h_src, scatter-atomicAdd into out1
__global__ void e1p2_kernel(const int* __restrict__ src, const int* __restrict__ dst) {
    int e = (blockIdx.x * blockDim.x + threadIdx.x) >> 5;
    int lane = threadIdx.x & 31;
    if (e >= E1) return;
    int s = src[e], d = dst[e];
    int h = lane >> 3;  // 8 lanes per head (8 ch each)
    float alpha = g_p1[(size_t)e * HEADS + h] / g_den1[(size_t)d * HEADS + h];
    const float* hs = g_h1 + (size_t)s * HD + lane * 8;
    float* ob = g_out1 + (size_t)d * HD + lane * 8;
    float4 v0 = *(const float4*)(hs);
    float4 v1 = *(const float4*)(hs + 4);
    atomicAdd(ob + 0, alpha * v0.x);
    atomicAdd(ob + 1, alpha * v0.y);
    atomicAdd(ob + 2, alpha * v0.z);
    atomicAdd(ob + 3, alpha * v0.w);
    atomicAdd(ob + 4, alpha * v1.x);
    atomicAdd(ob + 5, alpha * v1.y);
    atomicAdd(ob + 6, alpha * v1.z);
    atomicAdd(ob + 7, alpha * v1.w);
}

// ---------------- GEMM2: h2 = elu(bn(out1)) @ W2_src ----------------
// tile: 256 rows x 64 cols, 512 threads, thread = 2 rows x 16 cols, K chunks of 64
#define G2_SMEM ((HD * OUTD + 64 * 260) * 4)
__global__ __launch_bounds__(512) void gemm2_kernel(const float* __restrict__ W2s) {
    extern __shared__ float sm[];
    float* Wsm = sm;            // 256*64
    float* xs  = sm + HD * OUTD; // 64*260: xs[k*260 + r]
    int tid = threadIdx.x;
    int row0 = blockIdx.x * 256;
    for (int i = tid; i < HD * OUTD; i += 512) Wsm[i] = W2s[i];

    int tc = tid & 3, tr = tid >> 2;   // tr: 0..127 -> 2 rows, tc: 16 cols
    float acc[2][16];
#pragma unroll
    for (int a = 0; a < 2; a++)
#pragma unroll
        for (int b = 0; b < 16; b++) acc[a][b] = 0.f;

    for (int kb = 0; kb < HD; kb += 64) {
        __syncthreads();
        for (int i = tid; i < 64 * 256; i += 512) {
            int r = i >> 6, k = i & 63;
            int kg = kb + k;
            float v = g_out1[(size_t)(row0 + r) * HD + kg];
            v = v * g_bnscale[kg] + g_bnshift[kg];
            v = v > 0.f ? v : expm1f(v);
            xs[k * 260 + r] = v;
        }
        __syncthreads();
#pragma unroll 4
        for (int k = 0; k < 64; k++) {
            float2 xv = *(const float2*)(xs + k * 260 + tr * 2);
            const float* wr = Wsm + (kb + k) * OUTD + tc * 16;
            float4 w0 = *(const float4*)(wr);
            float4 w1 = *(const float4*)(wr + 4);
            float4 w2 = *(const float4*)(wr + 8);
            float4 w3 = *(const float4*)(wr + 12);
            float wv[16] = {w0.x, w0.y, w0.z, w0.w, w1.x, w1.y, w1.z, w1.w,
                            w2.x, w2.y, w2.z, w2.w, w3.x, w3.y, w3.z, w3.w};
#pragma unroll
            for (int b = 0; b < 16; b++) {
                acc[0][b] += xv.x * wv[b];
                acc[1][b] += xv.y * wv[b];
            }
        }
    }
#pragma unroll
    for (int a = 0; a < 2; a++) {
        float* o = g_h2 + (size_t)(row0 + tr * 2 + a) * OUTD + tc * 16;
        *(float4*)(o)      = make_float4(acc[a][0], acc[a][1], acc[a][2], acc[a][3]);
        *(float4*)(o + 4)  = make_float4(acc[a][4], acc[a][5], acc[a][6], acc[a][7]);
        *(float4*)(o + 8)  = make_float4(acc[a][8], acc[a][9], acc[a][10], acc[a][11]);
        *(float4*)(o + 12) = make_float4(acc[a][12], acc[a][13], acc[a][14], acc[a][15]);
    }
}

// ---------------- a2_src / a2_dst fold: warp per row ----------------
__global__ void a2_kernel() {
    int gw = (blockIdx.x * blockDim.x + threadIdx.x) >> 5;
    int lane = threadIdx.x & 31;
    if (gw >= N2) return;
    const float* row = g_out1 + (size_t)gw * HD + lane * 8;
    float4 r0 = *(const float4*)(row);
    float4 r1 = *(const float4*)(row + 4);
    float rv[8] = {r0.x, r0.y, r0.z, r0.w, r1.x, r1.y, r1.z, r1.w};
    float s = 0.f, d = 0.f;
#pragma unroll
    for (int i = 0; i < 8; i++) {
        int k = lane * 8 + i;
        float v = rv[i] * g_bnscale[k] + g_bnshift[k];
        v = v > 0.f ? v : expm1f(v);
        s += v * g_v2s[k];
        d += v * g_v2d[k];
    }
#pragma unroll
    for (int off = 16; off > 0; off >>= 1) {
        s += __shfl_down_sync(0xffffffffu, s, off);
        d += __shfl_down_sync(0xffffffffu, d, off);
    }
    if (lane == 0) {
        g_as2[gw] = s;
        if (gw < N3) g_ad2[gw] = d;
    }
}

// ---------------- edge passes layer 2 ----------------
__global__ void e2p1_kernel(const int* __restrict__ src, const int* __restrict__ dst) {
    int e = blockIdx.x * blockDim.x + threadIdx.x;
    if (e >= E2) return;
    int s = src[e], d = dst[e];
    float ee = g_as2[s] + g_ad2[d];
    ee = ee > 0.f ? ee : NEG_SLOPE * ee;
    float p = expf(ee);
    g_p2[e] = p;
    atomicAdd(&g_den2[d], p);
}

__global__ void initout_kernel(float* __restrict__ out, const float* __restrict__ b2) {
    int i = blockIdx.x * blockDim.x + threadIdx.x;
    if (i < N3 * OUTD) out[i] = b2[i & 63];
}

__global__ void e2p2_kernel(const int* __restrict__ src, const int* __restrict__ dst,
                            float* __restrict__ out) {
    int e = (blockIdx.x * blockDim.x + threadIdx.x) >> 5;
    int lane = threadIdx.x & 31;
    if (e >= E2) return;
    int s = src[e], d = dst[e];
    float alpha = g_p2[e] / g_den2[d];
    float2 v = *(const float2*)(g_h2 + (size_t)s * OUTD + lane * 2);
    atomicAdd(out + (size_t)d * OUTD + lane * 2, alpha * v.x);
    atomicAdd(out + (size_t)d * OUTD + lane * 2 + 1, alpha * v.y);
}

// ---------------- launch ----------------
extern "C" void kernel_launch(void* const* d_in, const int* in_sizes, int n_in,
                              void* d_out, int out_size) {
    const float* x        = (const float*)d_in[0];
    const float* W1_src   = (const float*)d_in[1];
    const float* W1_dst   = (const float*)d_in[2];
    const float* att1_src = (const float*)d_in[3];
    const float* att1_dst = (const float*)d_in[4];
    const float* b1       = (const float*)d_in[5];
    const float* gamma    = (const float*)d_in[6];
    const float* beta     = (const float*)d_in[7];
    const float* run_mean = (const float*)d_in[8];
    const float* run_var  = (const float*)d_in[9];
    const float* W2_src   = (const float*)d_in[10];
    const float* W2_dst   = (const float*)d_in[11];
    const float* att2_src = (const float*)d_in[12];
    const float* att2_dst = (const float*)d_in[13];
    const float* b2       = (const float*)d_in[14];
    const int*   src1     = (const int*)d_in[15];
    const int*   dst1     = (const int*)d_in[16];
    const int*   src2     = (const int*)d_in[17];
    const int*   dst2     = (const int*)d_in[18];
    float* out = (float*)d_out;

    cudaFuncSetAttribute(gemm1_kernel, cudaFuncAttributeMaxDynamicSharedMemorySize, G1_SMEM);
    cudaFuncSetAttribute(gemm2_kernel, cudaFuncAttributeMaxDynamicSharedMemorySize, G2_SMEM);

    void *p_den1 = nullptr, *p_out1 = nullptr, *p_den2 = nullptr;
    cudaGetSymbolAddress(&p_den1, g_den1);
    cudaGetSymbolAddress(&p_out1, g_out1);
    cudaGetSymbolAddress(&p_den2, g_den2);
    cudaMemsetAsync(p_den1, 0, (size_t)N2 * HEADS * sizeof(float), 0);
    cudaMemsetAsync(p_out1, 0, (size_t)N2 * HD * sizeof(float), 0);
    cudaMemsetAsync(p_den2, 0, (size_t)N3 * sizeof(float), 0);

    fold_kernel<<<1, 512>>>(W1_dst, att1_dst, W2_src, W2_dst, att2_src, att2_dst,
                            b1, gamma, beta, run_mean, run_var);

    gemm1_kernel<<<N1 / 128, 512, G1_SMEM>>>(x, W1_src, att1_src);
    adst1_kernel<<<N2 / 8, 256>>>(x);

    e1p1_kernel<<<E1 / 256, 256>>>(src1, dst1);
    e1p2_kernel<<<E1 / 8, 256>>>(src1, dst1);

    gemm2_kernel<<<N2 / 256, 512, G2_SMEM>>>(W2_src);
    a2_kernel<<<N2 / 8, 256>>>();

    initout_kernel<<<(N3 * OUTD) / 256, 256>>>(out, b2);
    e2p1_kernel<<<E2 / 256, 256>>>(src2, dst2);
    e2p2_kernel<<<E2 / 8, 256>>>(src2, dst2, out);
}

// round 2
// speedup vs baseline: 2.6379x; 2.6379x over previous
#include <cuda_runtime.h>
#include <cuda_bf16.h>
#include <cstdint>

#define N1 262144
#define N2 65536
#define N3 16384
#define E1 524288
#define E2 262144
#define HD 256
#define HID 64
#define HEADS 4
#define OUTD 64
#define IND 128
#define NEG_SLOPE 0.2f

// ---------------- device scratch ----------------
__device__ float g_as1[(size_t)N1 * HEADS];      // a_src layer1
__device__ float g_ad1[(size_t)N2 * HEADS];      // a_dst layer1
__device__ int   g_off1[N2 + 1];
__device__ int   g_cur1[N2];
__device__ int   g_srcs1[E1];
__device__ float g_alpha1[(size_t)E1 * HEADS];
__device__ float g_xagg[(size_t)N2 * HEADS * IND];  // 128 MB aggregated x per head
__device__ float g_hbn[(size_t)N2 * HD];            // elu(bn(out1)) 64 MB
__device__ float g_h2[(size_t)N2 * OUTD];           // 16 MB
__device__ float g_as2[N2];
__device__ float g_ad2[N3];
__device__ int   g_off2[N3 + 1];
__device__ int   g_cur2[N3];
__device__ int   g_srcs2[E2];
__device__ float g_alpha2[E2];

__device__ float g_v1s[IND * HEADS];   // fold W1_src@att1_src : [k][h]
__device__ float g_v1d[IND * HEADS];   // fold W1_dst@att1_dst
__device__ float g_v2s[HD];
__device__ float g_v2d[HD];
__device__ float g_bnscale[HD];
__device__ float g_bnshift[HD];

// ---------------- fold (tiny) ----------------
__global__ void fold_kernel(const float* __restrict__ W1s, const float* __restrict__ a1s,
                            const float* __restrict__ W1d, const float* __restrict__ a1d,
                            const float* __restrict__ W2s, const float* __restrict__ W2d,
                            const float* __restrict__ a2s, const float* __restrict__ a2d,
                            const float* __restrict__ b1, const float* __restrict__ gamma,
                            const float* __restrict__ beta, const float* __restrict__ mean,
                            const float* __restrict__ var) {
    int t = threadIdx.x;  // 512
    {
        int k = t >> 2, h = t & 3;
        float s1 = 0.f, d1 = 0.f;
        for (int c = 0; c < HID; c++) {
            s1 += W1s[k * HD + h * HID + c] * a1s[h * HID + c];
            d1 += W1d[k * HD + h * HID + c] * a1d[h * HID + c];
        }
        g_v1s[t] = s1;
        g_v1d[t] = d1;
    }
    if (t < HD) {
        float s2 = 0.f, d2 = 0.f;
        for (int c = 0; c < OUTD; c++) {
            s2 += W2s[t * OUTD + c] * a2s[c];
            d2 += W2d[t * OUTD + c] * a2d[c];
        }
        g_v2s[t] = s2;
        g_v2d[t] = d2;
        float sc = gamma[t] * rsqrtf(var[t] + 1e-5f);
        g_bnscale[t] = sc;
        g_bnshift[t] = beta[t] + (b1[t] - mean[t]) * sc;
    }
}

// ---------------- a_src1/a_dst1: warp per row of x ----------------
__global__ __launch_bounds__(256) void asrc1_kernel(const float* __restrict__ x) {
    __shared__ float sv1s[IND * HEADS], sv1d[IND * HEADS];
    int tid = threadIdx.x;
    for (int i = tid; i < IND * HEADS; i += 256) {
        sv1s[i] = g_v1s[i];
        sv1d[i] = g_v1d[i];
    }
    __syncthreads();
    int gw = (blockIdx.x * 256 + tid) >> 5;
    int lane = tid & 31;
    if (gw >= N1) return;
    float4 xv = *(const float4*)(x + (size_t)gw * IND + lane * 4);
    float xr[4] = {xv.x, xv.y, xv.z, xv.w};
    bool need_d = gw < N2;
    float s[4] = {0, 0, 0, 0}, dd[4] = {0, 0, 0, 0};
#pragma unroll
    for (int i = 0; i < 4; i++) {
        int k = lane * 4 + i;
#pragma unroll
        for (int h = 0; h < 4; h++) {
            s[h] += xr[i] * sv1s[k * HEADS + h];
            dd[h] += xr[i] * sv1d[k * HEADS + h];
        }
    }
#pragma unroll
    for (int off = 16; off > 0; off >>= 1)
#pragma unroll
        for (int h = 0; h < 4; h++) {
            s[h] += __shfl_down_sync(0xffffffffu, s[h], off);
            dd[h] += __shfl_down_sync(0xffffffffu, dd[h], off);
        }
    if (lane == 0) {
        *(float4*)(g_as1 + (size_t)gw * HEADS) = make_float4(s[0], s[1], s[2], s[3]);
        if (need_d)
            *(float4*)(g_ad1 + (size_t)gw * HEADS) = make_float4(dd[0], dd[1], dd[2], dd[3]);
    }
}

// ---------------- CSR build ----------------
__global__ void deg_kernel(const int* __restrict__ dst, int* __restrict__ cur, int n) {
    int i = blockIdx.x * blockDim.x + threadIdx.x;
    if (i < n) atomicAdd(&cur[dst[i]], 1);
}

__global__ __launch_bounds__(1024) void scan_kernel(int* __restrict__ cnt, int* __restrict__ off, int n) {
    __shared__ int sm[1024];
    int t = threadIdx.x;
    int chunk = n >> 10;
    int base = t * chunk;
    int s = 0;
    for (int i = 0; i < chunk; i++) s += cnt[base + i];
    sm[t] = s;
    __syncthreads();
    for (int d = 1; d < 1024; d <<= 1) {
        int v = (t >= d) ? sm[t - d] : 0;
        __syncthreads();
        sm[t] += v;
        __syncthreads();
    }
    int run = sm[t] - s;
    for (int i = 0; i < chunk; i++) {
        int c = cnt[base + i];
        off[base + i] = run;
        cnt[base + i] = run;  // cursor for fill
        run += c;
    }
    if (t == 1023) off[n] = run;
}

__global__ void fill_kernel(const int* __restrict__ src, const int* __restrict__ dst,
                            int* __restrict__ cur, int* __restrict__ srcs, int n) {
    int i = blockIdx.x * blockDim.x + threadIdx.x;
    if (i >= n) return;
    int pos = atomicAdd(&cur[dst[i]], 1);
    srcs[pos] = src[i];
}

// ---------------- layer1 softmax alphas: warp per dst ----------------
__global__ void alpha1_kernel() {
    int d = (blockIdx.x * blockDim.x + threadIdx.x) >> 5;
    int lane = threadIdx.x & 31;
    if (d >= N2) return;
    int beg = g_off1[d], end = g_off1[d + 1];
    if (beg == end) return;
    float4 adv = *(const float4*)(g_ad1 + (size_t)d * HEADS);
    float ad[4] = {adv.x, adv.y, adv.z, adv.w};
    float den[4] = {0, 0, 0, 0};
    for (int e = beg + lane; e < end; e += 32) {
        int s = g_srcs1[e];
        float4 asv = *(const float4*)(g_as1 + (size_t)s * HEADS);
        float as[4] = {asv.x, asv.y, asv.z, asv.w};
        float p[4];
#pragma unroll
        for (int h = 0; h < 4; h++) {
            float ee = as[h] + ad[h];
            ee = ee > 0.f ? ee : NEG_SLOPE * ee;
            p[h] = expf(ee);
            den[h] += p[h];
        }
        *(float4*)(g_alpha1 + (size_t)e * HEADS) = make_float4(p[0], p[1], p[2], p[3]);
    }
#pragma unroll
    for (int off = 16; off > 0; off >>= 1)
#pragma unroll
        for (int h = 0; h < 4; h++) den[h] += __shfl_xor_sync(0xffffffffu, den[h], off);
    float rd[4];
#pragma unroll
    for (int h = 0; h < 4; h++) rd[h] = 1.f / fmaxf(den[h], 1e-16f);
    for (int e = beg + lane; e < end; e += 32) {
        float4 p = *(const float4*)(g_alpha1 + (size_t)e * HEADS);
        *(float4*)(g_alpha1 + (size_t)e * HEADS) =
            make_float4(p.x * rd[0], p.y * rd[1], p.z * rd[2], p.w * rd[3]);
    }
}

// ---------------- layer1 aggregation of x: warp per dst ----------------
__global__ void agg1_kernel(const float* __restrict__ x) {
    int d = (blockIdx.x * blockDim.x + threadIdx.x) >> 5;
    int lane = threadIdx.x & 31;
    if (d >= N2) return;
    int beg = g_off1[d], end = g_off1[d + 1];
    float acc[4][4];
#pragma unroll
    for (int h = 0; h < 4; h++)
#pragma unroll
        for (int j = 0; j < 4; j++) acc[h][j] = 0.f;
    for (int e = beg; e < end; e++) {
        int s = g_srcs1[e];                                     // broadcast
        float4 al = *(const float4*)(g_alpha1 + (size_t)e * HEADS);  // broadcast
        float4 xv = *(const float4*)(x + (size_t)s * IND + lane * 4);
        float a[4] = {al.x, al.y, al.z, al.w};
        float xr[4] = {xv.x, xv.y, xv.z, xv.w};
#pragma unroll
        for (int h = 0; h < 4; h++)
#pragma unroll
            for (int j = 0; j < 4; j++) acc[h][j] += a[h] * xr[j];
    }
#pragma unroll
    for (int h = 0; h < 4; h++)
        *(float4*)(g_xagg + ((size_t)d * HEADS + h) * IND + lane * 4) =
            make_float4(acc[h][0], acc[h][1], acc[h][2], acc[h][3]);
}

// ---------------- GEMM-L1: hbn = elu(bn(xagg @ W1s_head)) ----------------
// block 256, tile 128 rows x 64 cols (one head), thread = 4 rows x 8 cols
#define GL1_SMEM ((IND * 64 + IND * 132) * 4)
__global__ __launch_bounds__(256) void gemm_l1_kernel(const float* __restrict__ W1s) {
    extern __shared__ float sm[];
    float* ws = sm;              // 128 x 64
    float* xs = sm + IND * 64;   // xs[k*132 + r], 128 k x 128 r
    int tid = threadIdx.x;
    int h = blockIdx.y;
    int row0 = blockIdx.x * 128;
    for (int i = tid; i < IND * 64; i += 256) {
        int k = i >> 6, c = i & 63;
        ws[i] = W1s[k * HD + h * HID + c];
    }
    for (int i = tid; i < IND * IND; i += 256) {
        int r = i >> 7, k = i & 127;
        xs[k * 132 + r] = g_xagg[((size_t)(row0 + r) * HEADS + h) * IND + k];
    }
    __syncthreads();
    int tc = tid & 7, tr = tid >> 3;   // tr 0..31 -> 4 rows, tc 0..7 -> 8 cols
    float acc[4][8];
#pragma unroll
    for (int a = 0; a < 4; a++)
#pragma unroll
        for (int b = 0; b < 8; b++) acc[a][b] = 0.f;
#pragma unroll 4
    for (int k = 0; k < IND; k++) {
        float4 xv = *(const float4*)(xs + k * 132 + tr * 4);
        float4 w0 = *(const float4*)(ws + k * 64 + tc * 8);
        float4 w1 = *(const float4*)(ws + k * 64 + tc * 8 + 4);
        float xr[4] = {xv.x, xv.y, xv.z, xv.w};
        float wv[8] = {w0.x, w0.y, w0.z, w0.w, w1.x, w1.y, w1.z, w1.w};
#pragma unroll
        for (int a = 0; a < 4; a++)
#pragma unroll
            for (int b = 0; b < 8; b++) acc[a][b] += xr[a] * wv[b];
    }
    float sc[8], sh[8];
#pragma unroll
    for (int b = 0; b < 8; b++) {
        int col = h * HID + tc * 8 + b;
        sc[b] = g_bnscale[col];
        sh[b] = g_bnshift[col];
    }
#pragma unroll
    for (int a = 0; a < 4; a++) {
        float vo[8];
#pragma unroll
        for (int b = 0; b < 8; b++) {
            float v = acc[a][b] * sc[b] + sh[b];
            vo[b] = v > 0.f ? v : expm1f(v);
        }
        float* o = g_hbn + (size_t)(row0 + tr * 4 + a) * HD + h * HID + tc * 8;
        *(float4*)(o)     = make_float4(vo[0], vo[1], vo[2], vo[3]);
        *(float4*)(o + 4) = make_float4(vo[4], vo[5], vo[6], vo[7]);
    }
}

// ---------------- a2 folds: warp per row of hbn ----------------
__global__ void a2_kernel() {
    int gw = (blockIdx.x * blockDim.x + threadIdx.x) >> 5;
    int lane = threadIdx.x & 31;
    if (gw >= N2) return;
    const float* row = g_hbn + (size_t)gw * HD + lane * 8;
    float4 r0 = *(const float4*)(row);
    float4 r1 = *(const float4*)(row + 4);
    float rv[8] = {r0.x, r0.y, r0.z, r0.w, r1.x, r1.y, r1.z, r1.w};
    float s = 0.f, d = 0.f;
#pragma unroll
    for (int i = 0; i < 8; i++) {
        int k = lane * 8 + i;
        s += rv[i] * g_v2s[k];
        d += rv[i] * g_v2d[k];
    }
#pragma unroll
    for (int off = 16; off > 0; off >>= 1) {
        s += __shfl_down_sync(0xffffffffu, s, off);
        d += __shfl_down_sync(0xffffffffu, d, off);
    }
    if (lane == 0) {
        g_as2[gw] = s;
        if (gw < N3) g_ad2[gw] = d;
    }
}

// ---------------- GEMM-L2: h2 = hbn @ W2s ----------------
// block 256, tile 128 rows x 64 cols, K=256 in 2 chunks of 128
#define GL2_SMEM ((IND * 64 + IND * 132) * 4)
__global__ __launch_bounds__(256) void gemm_l2_kernel(const float* __restrict__ W2s) {
    extern __shared__ float sm[];
    float* ws = sm;              // 128 x 64 (current K chunk)
    float* xs = sm + IND * 64;   // xs[k*132 + r]
    int tid = threadIdx.x;
    int row0 = blockIdx.x * 128;
    int tc = tid & 7, tr = tid >> 3;
    float acc[4][8];
#pragma unroll
    for (int a = 0; a < 4; a++)
#pragma unroll
        for (int b = 0; b < 8; b++) acc[a][b] = 0.f;
    for (int kb = 0; kb < HD; kb += 128) {
        __syncthreads();
        for (int i = tid; i < IND * 64; i += 256) {
            int k = i >> 6, c = i & 63;
            ws[i] = W2s[(kb + k) * OUTD + c];
        }
        for (int i = tid; i < IND * IND; i += 256) {
            int r = i >> 7, k = i & 127;
            xs[k * 132 + r] = g_hbn[(size_t)(row0 + r) * HD + kb + k];
        }
        __syncthreads();
#pragma unroll 4
        for (int k = 0; k < IND; k++) {
            float4 xv = *(const float4*)(xs + k * 132 + tr * 4);
            float4 w0 = *(const float4*)(ws + k * 64 + tc * 8);
            float4 w1 = *(const float4*)(ws + k * 64 + tc * 8 + 4);
            float xr[4] = {xv.x, xv.y, xv.z, xv.w};
            float wv[8] = {w0.x, w0.y, w0.z, w0.w, w1.x, w1.y, w1.z, w1.w};
#pragma unroll
            for (int a = 0; a < 4; a++)
#pragma unroll
                for (int b = 0; b < 8; b++) acc[a][b] += xr[a] * wv[b];
        }
    }
#pragma unroll
    for (int a = 0; a < 4; a++) {
        float* o = g_h2 + (size_t)(row0 + tr * 4 + a) * OUTD + tc * 8;
        *(float4*)(o)     = make_float4(acc[a][0], acc[a][1], acc[a][2], acc[a][3]);
        *(float4*)(o + 4) = make_float4(acc[a][4], acc[a][5], acc[a][6], acc[a][7]);
    }
}

// ---------------- layer2 alphas: warp per dst ----------------
__global__ void alpha2_kernel() {
    int d = (blockIdx.x * blockDim.x + threadIdx.x) >> 5;
    int lane = threadIdx.x & 31;
    if (d >= N3) return;
    int beg = g_off2[d], end = g_off2[d + 1];
    if (beg == end) return;
    float ad = g_ad2[d];
    float den = 0.f;
    for (int e = beg + lane; e < end; e += 32) {
        int s = g_srcs2[e];
        float ee = g_as2[s] + ad;
        ee = ee > 0.f ? ee : NEG_SLOPE * ee;
        float p = expf(ee);
        g_alpha2[e] = p;
        den += p;
    }
#pragma unroll
    for (int off = 16; off > 0; off >>= 1) den += __shfl_xor_sync(0xffffffffu, den, off);
    float rd = 1.f / fmaxf(den, 1e-16f);
    for (int e = beg + lane; e < end; e += 32) g_alpha2[e] *= rd;
}

// ---------------- layer2 aggregation into d_out: warp per dst ----------------
__global__ void agg2_kernel(float* __restrict__ out, const float* __restrict__ b2) {
    int d = (blockIdx.x * blockDim.x + threadIdx.x) >> 5;
    int lane = threadIdx.x & 31;
    if (d >= N3) return;
    int beg = g_off2[d], end = g_off2[d + 1];
    float ax = 0.f, ay = 0.f;
    for (int e = beg; e < end; e++) {
        int s = g_srcs2[e];           // broadcast
        float a = g_alpha2[e];        // broadcast
        float2 v = *(const float2*)(g_h2 + (size_t)s * OUTD + lane * 2);
        ax += a * v.x;
        ay += a * v.y;
    }
    out[(size_t)d * OUTD + lane * 2]     = ax + b2[lane * 2];
    out[(size_t)d * OUTD + lane * 2 + 1] = ay + b2[lane * 2 + 1];
}

// ---------------- launch ----------------
extern "C" void kernel_launch(void* const* d_in, const int* in_sizes, int n_in,
                              void* d_out, int out_size) {
    const float* x        = (const float*)d_in[0];
    const float* W1_src   = (const float*)d_in[1];
    const float* W1_dst   = (const float*)d_in[2];
    const float* att1_src = (const float*)d_in[3];
    const float* att1_dst = (const float*)d_in[4];
    const float* b1       = (const float*)d_in[5];
    const float* gamma    = (const float*)d_in[6];
    const float* beta     = (const float*)d_in[7];
    const float* run_mean = (const float*)d_in[8];
    const float* run_var  = (const float*)d_in[9];
    const float* W2_src   = (const float*)d_in[10];
    const float* W2_dst   = (const float*)d_in[11];
    const float* att2_src = (const float*)d_in[12];
    const float* att2_dst = (const float*)d_in[13];
    const float* b2       = (const float*)d_in[14];
    const int*   src1     = (const int*)d_in[15];
    const int*   dst1     = (const int*)d_in[16];
    const int*   src2     = (const int*)d_in[17];
    const int*   dst2     = (const int*)d_in[18];
    float* out = (float*)d_out;

    cudaFuncSetAttribute(gemm_l1_kernel, cudaFuncAttributeMaxDynamicSharedMemorySize, GL1_SMEM);
    cudaFuncSetAttribute(gemm_l2_kernel, cudaFuncAttributeMaxDynamicSharedMemorySize, GL2_SMEM);

    void *p_cur1 = nullptr, *p_cur2 = nullptr;
    int *d_off1 = nullptr, *d_cur1 = nullptr, *d_srcs1 = nullptr;
    int *d_off2 = nullptr, *d_cur2 = nullptr, *d_srcs2 = nullptr;
    cudaGetSymbolAddress(&p_cur1, g_cur1);
    cudaGetSymbolAddress(&p_cur2, g_cur2);
    d_cur1 = (int*)p_cur1;
    d_cur2 = (int*)p_cur2;
    void* tmp;
    cudaGetSymbolAddress(&tmp, g_off1);  d_off1 = (int*)tmp;
    cudaGetSymbolAddress(&tmp, g_srcs1); d_srcs1 = (int*)tmp;
    cudaGetSymbolAddress(&tmp, g_off2);  d_off2 = (int*)tmp;
    cudaGetSymbolAddress(&tmp, g_srcs2); d_srcs2 = (int*)tmp;

    cudaMemsetAsync(p_cur1, 0, N2 * sizeof(int), 0);
    cudaMemsetAsync(p_cur2, 0, N3 * sizeof(int), 0);

    fold_kernel<<<1, 512>>>(W1_src, att1_src, W1_dst, att1_dst, W2_src, W2_dst,
                            att2_src, att2_dst, b1, gamma, beta, run_mean, run_var);

    asrc1_kernel<<<N1 * 32 / 256, 256>>>(x);

    // CSR layer1
    deg_kernel<<<E1 / 256, 256>>>(dst1, d_cur1, E1);
    scan_kernel<<<1, 1024>>>(d_cur1, d_off1, N2);
    fill_kernel<<<E1 / 256, 256>>>(src1, dst1, d_cur1, d_srcs1, E1);
    alpha1_kernel<<<N2 / 8, 256>>>();
    agg1_kernel<<<N2 / 8, 256>>>(x);

    gemm_l1_kernel<<<dim3(N2 / 128, HEADS), 256, GL1_SMEM>>>(W1_src);
    a2_kernel<<<N2 / 8, 256>>>();

    // CSR layer2
    deg_kernel<<<E2 / 256, 256>>>(dst2, d_cur2, E2);
    scan_kernel<<<1, 1024>>>(d_cur2, d_off2, N3);
    fill_kernel<<<E2 / 256, 256>>>(src2, dst2, d_cur2, d_srcs2, E2);

    gemm_l2_kernel<<<N2 / 128, 256, GL2_SMEM>>>(W2_src);

    alpha2_kernel<<<N3 / 8, 256>>>();
    agg2_kernel<<<N3 / 8, 256>>>(out, b2);
}